// round 14
// baseline (speedup 1.0000x reference)
#include <cuda_runtime.h>
#include <cuda_bf16.h>
#include <cstdint>

#define B_    128
#define H_    14
#define W_    14
#define C4_   128           // C/4
#define CPB_  16            // c4 groups per block (64 channels)
#define NCLS_ 200
#define HWN_  196
#define TILE_ 28
#define NT_   7
#define TSTR_ 68            // tile row stride (floats): 272 B, 16B multiple
#define THR_  512
#define NHWG_ 32            // hw groups per block (2 per warp)

__global__ __launch_bounds__(THR_)
void fused_kernel(const float* __restrict__ x,
                  const float* __restrict__ gt,
                  const float* __restrict__ t_p,
                  const float* __restrict__ ct,
                  float* __restrict__ out) {
    __shared__ float4 sv4[THR_];                            // 8 KB
    __shared__ int4   si4[THR_];                            // 8 KB
    __shared__ int    s_plane[64];
    __shared__ int    s_cls;
    __shared__ __align__(16) float smem_t[TILE_ * TSTR_];   // 7.6 KB

    const int tid    = threadIdx.x;
    const int lane   = tid & 31;
    const int wid    = tid >> 5;
    const int lane16 = lane & 15;          // c4 within block
    const int hwg    = (wid << 1) | (lane >> 4);   // 0..31; == tid/16 index
    const int b      = blockIdx.y;
    const int c4     = blockIdx.x * CPB_ + lane16;

    const float4* x4 = (const float4*)x;
    const size_t bb4 = (size_t)b * HWN_ * C4_;

    // ---- cls[b] = argmax(gt[b,:200]) — warp 0 via shfl ----
    if (wid == 0) {
        const float* g = gt + (size_t)b * NCLS_;
        float bv = -1e30f; int bi = NCLS_;
        for (int i = lane; i < NCLS_; i += 32) {
            float v = __ldg(g + i);
            if (v > bv) { bv = v; bi = i; }
        }
        #pragma unroll
        for (int s = 16; s > 0; s >>= 1) {
            float ov = __shfl_down_sync(0xffffffffu, bv, s);
            int   oi = __shfl_down_sync(0xffffffffu, bi, s);
            if (ov > bv || (ov == bv && oi < bi)) { bv = ov; bi = oi; }
        }
        if (lane == 0) s_cls = bi;
    }

    // ---- phase 1: spatial argmax; 4 channels/thread, hw interleaved by 32 ----
    float mv[4] = {-1e30f, -1e30f, -1e30f, -1e30f};
    int   mi[4] = {0, 0, 0, 0};
    for (int hw = hwg; hw < HWN_; hw += NHWG_) {
        float4 v = __ldg(&x4[bb4 + (size_t)hw * C4_ + c4]);
        if (v.x > mv[0]) { mv[0] = v.x; mi[0] = hw; }
        if (v.y > mv[1]) { mv[1] = v.y; mi[1] = hw; }
        if (v.z > mv[2]) { mv[2] = v.z; mi[2] = hw; }
        if (v.w > mv[3]) { mv[3] = v.w; mi[3] = hw; }
    }
    // table layout: index = hwg*16 + lane16 == tid
    sv4[tid] = make_float4(mv[0], mv[1], mv[2], mv[3]);
    si4[tid] = make_int4(mi[0], mi[1], mi[2], mi[3]);
    __syncthreads();

    if (tid < CPB_) {
        float bm[4] = {-1e30f, -1e30f, -1e30f, -1e30f};
        int   bx[4] = {0, 0, 0, 0};
        #pragma unroll
        for (int g2 = 0; g2 < NHWG_; ++g2) {
            float4 v = sv4[g2 * CPB_ + tid];
            int4   i = si4[g2 * CPB_ + tid];
            if (v.x > bm[0] || (v.x == bm[0] && i.x < bx[0])) { bm[0]=v.x; bx[0]=i.x; }
            if (v.y > bm[1] || (v.y == bm[1] && i.y < bx[1])) { bm[1]=v.y; bx[1]=i.y; }
            if (v.z > bm[2] || (v.z == bm[2] && i.z < bx[2])) { bm[2]=v.z; bx[2]=i.z; }
            if (v.w > bm[3] || (v.w == bm[3] && i.w < bx[3])) { bm[3]=v.w; bx[3]=i.w; }
        }
        #pragma unroll
        for (int i = 0; i < 4; ++i) {
            int hh = bx[i] / W_;
            int ww = bx[i] - hh * W_;
            if (bm[i] == 0.0f) { hh = H_; ww = W_; }   // sentinel
            s_plane[tid * 4 + i] = (hh * (W_ + 1) + ww) * HWN_;
        }
    }
    __syncthreads();

    // ---- phase 2: tiled vectorized elementwise ----
    const int cls = s_cls;
    const float4* ct4 = (const float4*)ct;
    const size_t ctb4 = (size_t)cls * HWN_ * C4_ + c4;
    const size_t psz4 = (size_t)B_ * HWN_ * C4_;
    float4* o4 = (float4*)out;

    for (int t = 0; t < NT_; ++t) {
        const int hw0 = t * TILE_;

        // stage: warp wid stages channels [wid*4, wid*4+4); lanes 0..27 = hw
        #pragma unroll
        for (int j = 0; j < 4; ++j) {
            int ch = (wid << 2) + j;
            if (lane < TILE_)
                smem_t[lane * TSTR_ + ch] = __ldg(t_p + s_plane[ch] + hw0 + lane);
        }
        __syncthreads();

        // compute: one float4 slot per thread, k = hwg (0..31), active k<28
        if (hwg < TILE_) {
            const int hw = hw0 + hwg;
            const size_t off = bb4 + (size_t)hw * C4_ + c4;
            float4 xv = __ldg(&x4[off]);
            float4 cv = __ldg(&ct4[ctb4 + (size_t)hw * C4_]);
            float4 tv = *(const float4*)&smem_t[hwg * TSTR_ + lane16 * 4];
            float4 m;
            m.x = fmaxf(xv.x * tv.x, 0.0f) * cv.x;
            m.y = fmaxf(xv.y * tv.y, 0.0f) * cv.y;
            m.z = fmaxf(xv.z * tv.z, 0.0f) * cv.z;
            m.w = fmaxf(xv.w * tv.w, 0.0f) * cv.w;
            o4[off]            = m;
            o4[psz4 + off]     = xv;
            o4[2 * psz4 + off] = tv;
        }
        __syncthreads();
    }
}

extern "C" void kernel_launch(void* const* d_in, const int* in_sizes, int n_in,
                              void* d_out, int out_size) {
    const float* x  = (const float*)d_in[0];
    const float* gt = (const float*)d_in[1];
    const float* tp = (const float*)d_in[2];
    const float* ct = (const float*)d_in[3];
    float* out = (float*)d_out;

    fused_kernel<<<dim3(C4_ / CPB_, B_), THR_>>>(x, gt, tp, ct, out);
}

// round 15
// speedup vs baseline: 1.5076x; 1.5076x over previous
#include <cuda_runtime.h>
#include <cuda_bf16.h>
#include <cstdint>

#define B_    128
#define H_    14
#define W_    14
#define C4_   128           // C/4
#define NCLS_ 200
#define HWN_  196
#define TILE_ 28
#define NT_   7
#define TSTR_ 132           // [k][ch] row stride (floats): 528 B, 16B multiple
#define NWRP_ 16

// scratch: per (b, c4 group) the 4 channels' t_p plane offsets
__device__ int4 g_plane4[B_ * C4_];
__device__ int  g_cls[B_];

// ---------------------------------------------------------------------------
// K1: per-channel spatial argmax (+ cls argmax) — R6 phase-1 geometry
// grid (4, 128), 512 threads, 32 regs
// ---------------------------------------------------------------------------
__global__ __launch_bounds__(512, 4)
void argmax_kernel(const float* __restrict__ x,
                   const float* __restrict__ gt) {
    __shared__ float4 sv4[512];
    __shared__ int4   si4[512];

    const int tid  = threadIdx.x;
    const int lane = tid & 31;
    const int hwg  = tid >> 5;
    const int b    = blockIdx.y;
    const int c4   = blockIdx.x * 32 + lane;

    const float4* x4 = (const float4*)x;
    const size_t bb4 = (size_t)b * HWN_ * C4_;

    // cls[b] — warp 0
    if (hwg == 0) {
        const float* g = gt + (size_t)b * NCLS_;
        float bv = -1e30f; int bi = NCLS_;
        for (int i = lane; i < NCLS_; i += 32) {
            float v = __ldg(g + i);
            if (v > bv) { bv = v; bi = i; }
        }
        #pragma unroll
        for (int s = 16; s > 0; s >>= 1) {
            float ov = __shfl_down_sync(0xffffffffu, bv, s);
            int   oi = __shfl_down_sync(0xffffffffu, bi, s);
            if (ov > bv || (ov == bv && oi < bi)) { bv = ov; bi = oi; }
        }
        if (lane == 0) g_cls[b] = bi;
    }

    float mv[4] = {-1e30f, -1e30f, -1e30f, -1e30f};
    int   mi[4] = {0, 0, 0, 0};
    for (int hw = hwg; hw < HWN_; hw += NWRP_) {
        float4 v = __ldg(&x4[bb4 + (size_t)hw * C4_ + c4]);
        if (v.x > mv[0]) { mv[0] = v.x; mi[0] = hw; }
        if (v.y > mv[1]) { mv[1] = v.y; mi[1] = hw; }
        if (v.z > mv[2]) { mv[2] = v.z; mi[2] = hw; }
        if (v.w > mv[3]) { mv[3] = v.w; mi[3] = hw; }
    }
    sv4[tid] = make_float4(mv[0], mv[1], mv[2], mv[3]);
    si4[tid] = make_int4(mi[0], mi[1], mi[2], mi[3]);
    __syncthreads();

    if (tid < 32) {
        float bm[4] = {-1e30f, -1e30f, -1e30f, -1e30f};
        int   bx[4] = {0, 0, 0, 0};
        #pragma unroll
        for (int g2 = 0; g2 < NWRP_; ++g2) {
            float4 v = sv4[g2 * 32 + tid];
            int4   i = si4[g2 * 32 + tid];
            if (v.x > bm[0] || (v.x == bm[0] && i.x < bx[0])) { bm[0]=v.x; bx[0]=i.x; }
            if (v.y > bm[1] || (v.y == bm[1] && i.y < bx[1])) { bm[1]=v.y; bx[1]=i.y; }
            if (v.z > bm[2] || (v.z == bm[2] && i.z < bx[2])) { bm[2]=v.z; bx[2]=i.z; }
            if (v.w > bm[3] || (v.w == bm[3] && i.w < bx[3])) { bm[3]=v.w; bx[3]=i.w; }
        }
        int4 pl;
        int* p = &pl.x;
        #pragma unroll
        for (int i = 0; i < 4; ++i) {
            int hh = bx[i] / W_;
            int ww = bx[i] - hh * W_;
            if (bm[i] == 0.0f) { hh = H_; ww = W_; }   // sentinel
            p[i] = (hh * (W_ + 1) + ww) * HWN_;
        }
        g_plane4[b * C4_ + blockIdx.x * 32 + tid] = pl;
    }
}

// ---------------------------------------------------------------------------
// K2: elementwise over one 28-hw tile; grid (4, 128, 7), 256 threads
// lane = c4 (32 -> 128 channels/block), 8 hw-groups
// ---------------------------------------------------------------------------
__global__ __launch_bounds__(256, 8)
void ewise_kernel(const float* __restrict__ x,
                  const float* __restrict__ t_p,
                  const float* __restrict__ ct,
                  float* __restrict__ out) {
    __shared__ __align__(16) float smem_t[TILE_ * TSTR_];   // 14.8 KB
    __shared__ int s_plane[128];
    __shared__ int s_cls;

    const int tid  = threadIdx.x;
    const int lane = tid & 31;             // c4 within block
    const int hwg  = tid >> 5;             // 0..7
    const int b    = blockIdx.y;
    const int hw0  = blockIdx.z * TILE_;
    const int c4   = blockIdx.x * 32 + lane;

    // load plane offsets (128 ints = 32 int4) + cls
    if (tid < 32) {
        int4 pl = __ldg(&g_plane4[b * C4_ + blockIdx.x * 32 + tid]);
        s_plane[tid * 4 + 0] = pl.x;
        s_plane[tid * 4 + 1] = pl.y;
        s_plane[tid * 4 + 2] = pl.z;
        s_plane[tid * 4 + 3] = pl.w;
    }
    if (tid == 0) s_cls = __ldg(&g_cls[b]);
    __syncthreads();

    // stage templates: warp hwg stages channels [hwg*16, hwg*16+16)
    #pragma unroll
    for (int j = 0; j < 16; ++j) {
        int ch = hwg * 16 + j;
        if (lane < TILE_)
            smem_t[lane * TSTR_ + ch] = __ldg(t_p + s_plane[ch] + hw0 + lane);
    }
    __syncthreads();

    const float4* x4  = (const float4*)x;
    const float4* ct4 = (const float4*)ct;
    const size_t bb4  = (size_t)b * HWN_ * C4_;
    const size_t ctb4 = (size_t)s_cls * HWN_ * C4_ + c4;
    const size_t psz4 = (size_t)B_ * HWN_ * C4_;
    float4* o4 = (float4*)out;

    for (int k = hwg; k < TILE_; k += 8) {
        const int hw = hw0 + k;
        const size_t off = bb4 + (size_t)hw * C4_ + c4;
        float4 xv = __ldg(&x4[off]);
        float4 cv = __ldg(&ct4[ctb4 + (size_t)hw * C4_]);
        float4 tv = *(const float4*)&smem_t[k * TSTR_ + lane * 4];
        float4 m;
        m.x = fmaxf(xv.x * tv.x, 0.0f) * cv.x;
        m.y = fmaxf(xv.y * tv.y, 0.0f) * cv.y;
        m.z = fmaxf(xv.z * tv.z, 0.0f) * cv.z;
        m.w = fmaxf(xv.w * tv.w, 0.0f) * cv.w;
        o4[off]            = m;
        o4[psz4 + off]     = xv;
        o4[2 * psz4 + off] = tv;
    }
}

extern "C" void kernel_launch(void* const* d_in, const int* in_sizes, int n_in,
                              void* d_out, int out_size) {
    const float* x  = (const float*)d_in[0];
    const float* gt = (const float*)d_in[1];
    const float* tp = (const float*)d_in[2];
    const float* ct = (const float*)d_in[3];
    float* out = (float*)d_out;

    argmax_kernel<<<dim3(C4_ / 32, B_), 512>>>(x, gt);
    ewise_kernel<<<dim3(C4_ / 32, B_, NT_), 256>>>(x, tp, ct, out);
}

// round 17
// speedup vs baseline: 1.5951x; 1.0581x over previous
#include <cuda_runtime.h>
#include <cuda_bf16.h>
#include <cstdint>

#define B_    128
#define H_    14
#define W_    14
#define C4_   128           // C/4
#define NCLS_ 200
#define HWN_  196
#define TILE_ 28
#define NT_   7
#define TSTR_ 132           // row stride (floats): 528 B, 16B multiple -> aligned LDS.128
#define THR_  512
#define NWRP_ 16

__global__ __launch_bounds__(THR_, 4)
void fused_kernel(const float* __restrict__ x,
                  const float* __restrict__ gt,
                  const float* __restrict__ t_p,
                  const float* __restrict__ ct,
                  float* __restrict__ out) {
    __shared__ float4 sv4[THR_];             // 8 KB
    __shared__ int4   si4[THR_];             // 8 KB
    __shared__ int    s_plane[128];
    __shared__ int    s_cls;
    __shared__ __align__(16) float smem_t[TILE_ * TSTR_];   // 14.8 KB

    const int tid  = threadIdx.x;
    const int lane = tid & 31;               // float4 channel-group
    const int hwg  = tid >> 5;               // warp id == hw group (0..15)
    const int b    = blockIdx.y;
    const int c4   = blockIdx.x * 32 + lane;

    const float4* x4 = (const float4*)x;
    const size_t bb4 = (size_t)b * HWN_ * C4_;
    const size_t psz4 = (size_t)B_ * HWN_ * C4_;
    float4* o4 = (float4*)out;

    // ---- cls[b] = argmax(gt[b,:200]) — warp 0 via shfl ----
    if (hwg == 0) {
        const float* g = gt + (size_t)b * NCLS_;
        float bv = -1e30f; int bi = NCLS_;
        for (int i = lane; i < NCLS_; i += 32) {
            float v = __ldg(g + i);
            if (v > bv) { bv = v; bi = i; }
        }
        #pragma unroll
        for (int s = 16; s > 0; s >>= 1) {
            float ov = __shfl_down_sync(0xffffffffu, bv, s);
            int   oi = __shfl_down_sync(0xffffffffu, bi, s);
            if (ov > bv || (ov == bv && oi < bi)) { bv = ov; bi = oi; }
        }
        if (lane == 0) s_cls = bi;
    }

    // ---- phase 1: spatial argmax + x passthrough write (free direction) ----
    float mv[4] = {-1e30f, -1e30f, -1e30f, -1e30f};
    int   mi[4] = {0, 0, 0, 0};
    for (int hw = hwg; hw < HWN_; hw += NWRP_) {
        const size_t off = bb4 + (size_t)hw * C4_ + c4;
        float4 v = __ldg(&x4[off]);
        o4[psz4 + off] = v;                  // x passthrough, written here once
        if (v.x > mv[0]) { mv[0] = v.x; mi[0] = hw; }
        if (v.y > mv[1]) { mv[1] = v.y; mi[1] = hw; }
        if (v.z > mv[2]) { mv[2] = v.z; mi[2] = hw; }
        if (v.w > mv[3]) { mv[3] = v.w; mi[3] = hw; }
    }
    sv4[tid] = make_float4(mv[0], mv[1], mv[2], mv[3]);
    si4[tid] = make_int4(mi[0], mi[1], mi[2], mi[3]);
    __syncthreads();

    if (tid < 32) {
        float bm[4] = {-1e30f, -1e30f, -1e30f, -1e30f};
        int   bx[4] = {0, 0, 0, 0};
        #pragma unroll
        for (int g2 = 0; g2 < NWRP_; ++g2) {
            float4 v = sv4[g2 * 32 + tid];
            int4   i = si4[g2 * 32 + tid];
            if (v.x > bm[0] || (v.x == bm[0] && i.x < bx[0])) { bm[0]=v.x; bx[0]=i.x; }
            if (v.y > bm[1] || (v.y == bm[1] && i.y < bx[1])) { bm[1]=v.y; bx[1]=i.y; }
            if (v.z > bm[2] || (v.z == bm[2] && i.z < bx[2])) { bm[2]=v.z; bx[2]=i.z; }
            if (v.w > bm[3] || (v.w == bm[3] && i.w < bx[3])) { bm[3]=v.w; bx[3]=i.w; }
        }
        #pragma unroll
        for (int i = 0; i < 4; ++i) {
            int hh = bx[i] / W_;
            int ww = bx[i] - hh * W_;
            if (bm[i] == 0.0f) { hh = H_; ww = W_; }   // sentinel
            s_plane[tid * 4 + i] = (hh * (W_ + 1) + ww) * HWN_;
        }
    }
    __syncthreads();

    // ---- phase 2: tiled elementwise; x re-read hits L2; 2 stores/iter ----
    const int cls = s_cls;
    const float4* ct4 = (const float4*)ct;
    const size_t ctb4 = (size_t)cls * HWN_ * C4_ + c4;

    for (int t = 0; t < NT_; ++t) {
        const int hw0 = t * TILE_;

        // stage templates: warp hwg stages channels [hwg*8, hwg*8+8)
        #pragma unroll
        for (int j = 0; j < 8; ++j) {
            int ch = hwg * 8 + j;
            if (lane < TILE_)
                smem_t[lane * TSTR_ + ch] = __ldg(t_p + s_plane[ch] + hw0 + lane);
        }
        __syncthreads();

        for (int k = hwg; k < TILE_; k += NWRP_) {
            const int hw = hw0 + k;
            const size_t off = bb4 + (size_t)hw * C4_ + c4;
            float4 xv = __ldg(&x4[off]);
            float4 cv = __ldg(&ct4[ctb4 + (size_t)hw * C4_]);
            float4 tv = *(const float4*)&smem_t[k * TSTR_ + lane * 4];
            float4 m;
            m.x = fmaxf(xv.x * tv.x, 0.0f) * cv.x;
            m.y = fmaxf(xv.y * tv.y, 0.0f) * cv.y;
            m.z = fmaxf(xv.z * tv.z, 0.0f) * cv.z;
            m.w = fmaxf(xv.w * tv.w, 0.0f) * cv.w;
            o4[off]            = m;
            o4[2 * psz4 + off] = tv;
        }
        __syncthreads();
    }
}

extern "C" void kernel_launch(void* const* d_in, const int* in_sizes, int n_in,
                              void* d_out, int out_size) {
    const float* x  = (const float*)d_in[0];
    const float* gt = (const float*)d_in[1];
    const float* tp = (const float*)d_in[2];
    const float* ct = (const float*)d_in[3];
    float* out = (float*)d_out;

    fused_kernel<<<dim3(C4_ / 32, B_), THR_>>>(x, gt, tp, ct, out);
}